// round 16
// baseline (speedup 1.0000x reference)
#include <cuda_runtime.h>
#include <cuda_bf16.h>
#include <cstdint>

// ---------------- problem constants ----------------
#define B_TOT 16384
#define F_TOT 32
#define D_IN  64
#define H_HID 128

#define THREADS       256
#define TILES         4
#define ROWS_PER_TILE 64
#define ROWS_PER_BLK  (TILES * ROWS_PER_TILE)   // 256

// smem float layout: A double-buffered (raw fp32), B transposed [h][k] (tf32)
#define A_STRIDE  68                      // 272B rows: 8-row LDSM phases distinct
#define B2_STRIDE 68
#define A_FLOATS  (ROWS_PER_TILE * A_STRIDE)   // 4352
#define B2_FLOATS (128 * B2_STRIDE)            // 8704
#define B_OFF     (2 * A_FLOATS)               // 8704
#define B1_OFF    (B_OFF + B2_FLOATS)          // b1s[128]
#define W2_OFF    (B1_OFF + 128)               // w2s[128]
#define EP_OFF    (W2_OFF + 128)               // ep[2][64][4]
#define SMEM_FLOATS (EP_OFF + 512)             // 18176
#define SMEM_BYTES  (SMEM_FLOATS * 4)          // 72704 -> 3 CTAs = 218KB < 228KB

__device__ __forceinline__ float to_tf32(float x) {
    float y;
    asm("cvt.rna.tf32.f32 %0, %1;" : "=f"(y) : "f"(x));
    return y;
}
__device__ __forceinline__ uint32_t smem_u32(const void* p) {
    uint32_t a;
    asm("{ .reg .u64 t; cvta.to.shared.u64 t, %1; cvt.u32.u64 %0, t; }" : "=r"(a) : "l"(p));
    return a;
}

#define CP_ASYNC16(dst_u32, src_ptr) \
    asm volatile("cp.async.cg.shared.global [%0], [%1], 16;" \
                 :: "r"(dst_u32), "l"(src_ptr) : "memory")
#define CP_ASYNC_COMMIT() asm volatile("cp.async.commit_group;" ::: "memory")
#define CP_ASYNC_WAIT(n)  asm volatile("cp.async.wait_group %0;" :: "n"(n) : "memory")

// ldmatrix (b16 view): 8x8 b16 matrix = 8 rows x 16B; as b32, lane L of
// matrix m receives element (row L/4, col L%4).
#define LDSM_X4(r0, r1, r2, r3, addr) \
    asm volatile("ldmatrix.sync.aligned.m8n8.x4.shared.b16 {%0,%1,%2,%3}, [%4];" \
                 : "=r"(r0), "=r"(r1), "=r"(r2), "=r"(r3) : "r"(addr))

// m16n8k8 row.col tf32 MMA, fp32 accumulate
#define MMA_TF32(c, a, b0r, b1r)                                          \
    asm volatile("mma.sync.aligned.m16n8k8.row.col.f32.tf32.tf32.f32 "    \
                 "{%0,%1,%2,%3}, {%4,%5,%6,%7}, {%8,%9}, {%0,%1,%2,%3};"  \
                 : "+f"((c)[0]), "+f"((c)[1]), "+f"((c)[2]), "+f"((c)[3]) \
                 : "r"((a)[0]), "r"((a)[1]), "r"((a)[2]), "r"((a)[3]),    \
                   "r"(b0r), "r"(b1r))

__global__ void __launch_bounds__(THREADS, 3)
cont_mlp_mma_kernel(const float* __restrict__ X,
                    const float* __restrict__ r_,
                    const float* __restrict__ W1,
                    const float* __restrict__ b1,
                    const float* __restrict__ W2,
                    const float* __restrict__ b2,
                    float* __restrict__ out)
{
    extern __shared__ float sm[];
    float* B_s  = sm + B_OFF;     // [128 h][68 k], tf32
    float* b1s  = sm + B1_OFF;    // [128]
    float* w2s  = sm + W2_OFF;    // [128]
    float* ep   = sm + EP_OFF;    // [2][64][4] double-buffered partials
    const uint32_t smb = smem_u32(sm);

    const int f        = blockIdx.y;
    const int rowbase0 = blockIdx.x * ROWS_PER_BLK;
    const int t        = threadIdx.x;

    const int wid  = t >> 5;
    const int lane = t & 31;
    const int mgrp = wid & 1;       // rows [mgrp*32, +32)
    const int ngrp = wid >> 1;      // cols [ngrp*32, +32)
    const int qrow = lane >> 2;     // 0..7
    const int qcol = lane & 3;      // 0..3

    const float* rfeat = r_ + (size_t)f * D_IN;   // row stride = F_TOT*D_IN floats

    // ---- issue cp.async for tile 0 into buffer 0 (raw fp32) ----
    {
        const float* rbase = rfeat + (size_t)rowbase0 * (F_TOT * D_IN);
        #pragma unroll
        for (int i = 0; i < 4; ++i) {
            int idx = t + i * THREADS;      // 0..1023 float4 units
            int row = idx >> 4;             // 0..63
            int q   = idx & 15;
            uint32_t dst = smb + (uint32_t)((row * A_STRIDE + q * 4) * 4);
            CP_ASYNC16(dst, rbase + (size_t)row * (F_TOT * D_IN) + q * 4);
        }
        CP_ASYNC_COMMIT();
    }

    // ---- stage B = W1[f] transposed to [h][k], tf32-rounded, conflict-free ----
    {
        const float* Wf = W1 + (size_t)f * D_IN * H_HID;
        #pragma unroll
        for (int i = 0; i < 8; ++i) {
            int idx = t + i * THREADS;      // 0..2047
            int h   = idx & 127;            // lane-consecutive -> coalesced LDG
            int d0  = (idx >> 7) * 4;       // k block 0..60
            float4 v;
            v.x = to_tf32(Wf[(d0 + 0) * H_HID + h]);
            v.y = to_tf32(Wf[(d0 + 1) * H_HID + h]);
            v.z = to_tf32(Wf[(d0 + 2) * H_HID + h]);
            v.w = to_tf32(Wf[(d0 + 3) * H_HID + h]);
            *reinterpret_cast<float4*>(B_s + h * B2_STRIDE + d0) = v;
        }
    }
    if (t < H_HID) {
        b1s[t] = b1[f * H_HID + t];
        w2s[t] = W2[f * H_HID + t];
    }
    const float b2v = b2[f];

    // ---- per-thread ldmatrix base addresses ----
    // A x4: matrices {r+0,k0}{r+8,k0}{r+0,k4}{r+8,k4}, r = mgrp*32 (+mt*16)
    const uint32_t a_base_off = (uint32_t)((
        (mgrp * 32 + (lane & 7) + ((lane >> 3) & 1) * 8) * A_STRIDE
        + (lane >> 4) * 4) * 4);
    // B x4: matrices {n+0,k0}{n+0,k4}{n+8,k0}{n+8,k4}, n = ngrp*32 (+ntp*16)
    const uint32_t b_base = smb + (uint32_t)(B_OFF * 4) + (uint32_t)((
        (ngrp * 32 + (lane & 7) + ((lane >> 4) & 1) * 8) * B2_STRIDE
        + ((lane >> 3) & 1) * 4) * 4);

    #pragma unroll 1
    for (int tile = 0; tile < TILES; ++tile) {
        CP_ASYNC_WAIT(0);         // group(tile) complete (issued last iteration)
        __syncthreads();          // A[tile&1] visible; prior kloop reads done; ep(t-1) visible

        // ---- output for previous tile (reads ep[(tile-1)&1]) ----
        if (tile > 0 && t < ROWS_PER_TILE) {
            const float* epb = ep + ((tile - 1) & 1) * 256;
            float s  = epb[t * 4 + 0] + epb[t * 4 + 1]
                     + epb[t * 4 + 2] + epb[t * 4 + 3];
            float y  = fmaxf(s + b2v, 0.0f);
            int rowg = rowbase0 + (tile - 1) * ROWS_PER_TILE + t;
            float xv = X[(size_t)rowg * F_TOT + f];
            reinterpret_cast<float2*>(out)[(size_t)rowg * F_TOT + f] =
                make_float2(xv, y);
        }

        // ---- issue cp.async for tile+1 (safe: all passed the barrier) ----
        if (tile + 1 < TILES) {
            const float* rbase = rfeat +
                (size_t)(rowbase0 + (tile + 1) * ROWS_PER_TILE) * (F_TOT * D_IN);
            uint32_t abuf = smb + (uint32_t)(((tile + 1) & 1) * A_FLOATS * 4);
            #pragma unroll
            for (int i = 0; i < 4; ++i) {
                int idx = t + i * THREADS;
                int row = idx >> 4;
                int q   = idx & 15;
                uint32_t dst = abuf + (uint32_t)((row * A_STRIDE + q * 4) * 4);
                CP_ASYNC16(dst, rbase + (size_t)row * (F_TOT * D_IN) + q * 4);
            }
            CP_ASYNC_COMMIT();
        }

        float acc[2][4][4];
        #pragma unroll
        for (int mt = 0; mt < 2; ++mt)
            #pragma unroll
            for (int nt = 0; nt < 4; ++nt)
                #pragma unroll
                for (int rr = 0; rr < 4; ++rr)
                    acc[mt][nt][rr] = 0.0f;

        const uint32_t a_base = smb + (uint32_t)((tile & 1) * A_FLOATS * 4) + a_base_off;

        // ---- k-loop: 8 steps of k=8; LDSM.x4, A rounded in regs ----
        #pragma unroll
        for (int ks = 0; ks < 8; ++ks) {
            uint32_t a[2][4];
            #pragma unroll
            for (int mt = 0; mt < 2; ++mt) {
                LDSM_X4(a[mt][0], a[mt][1], a[mt][2], a[mt][3],
                        a_base + (uint32_t)(mt * 16 * A_STRIDE * 4) + (uint32_t)(ks * 32));
                #pragma unroll
                for (int rr = 0; rr < 4; ++rr)
                    a[mt][rr] = __float_as_uint(to_tf32(__uint_as_float(a[mt][rr])));
            }
            #pragma unroll
            for (int ntp = 0; ntp < 2; ++ntp) {
                uint32_t b0, b1r, b2r, b3r;   // {nt.b0, nt.b1, nt+8.b0, nt+8.b1}
                LDSM_X4(b0, b1r, b2r, b3r,
                        b_base + (uint32_t)(ntp * 16 * B2_STRIDE * 4) + (uint32_t)(ks * 32));
                #pragma unroll
                for (int mt = 0; mt < 2; ++mt) {
                    MMA_TF32(acc[mt][2 * ntp + 0], a[mt], b0, b1r);
                    MMA_TF32(acc[mt][2 * ntp + 1], a[mt], b2r, b3r);
                }
            }
        }

        // ---- epilogue: relu(+b1)*w2, sum over this warp's 32 cols ----
        float part[2][2] = {{0.0f, 0.0f}, {0.0f, 0.0f}};
        #pragma unroll
        for (int nt = 0; nt < 4; ++nt) {
            int c = ngrp * 32 + nt * 8 + qcol * 2;
            float2 bp = *reinterpret_cast<const float2*>(b1s + c);
            float2 wp = *reinterpret_cast<const float2*>(w2s + c);
            #pragma unroll
            for (int mt = 0; mt < 2; ++mt)
                #pragma unroll
                for (int hf = 0; hf < 2; ++hf) {
                    float d0 = fmaxf(acc[mt][nt][hf * 2 + 0] + bp.x, 0.0f);
                    float d1 = fmaxf(acc[mt][nt][hf * 2 + 1] + bp.y, 0.0f);
                    part[mt][hf] = fmaf(d0, wp.x, part[mt][hf]);
                    part[mt][hf] = fmaf(d1, wp.y, part[mt][hf]);
                }
        }
        // quad reduce across qcol
        #pragma unroll
        for (int off = 1; off < 4; off <<= 1)
            #pragma unroll
            for (int mt = 0; mt < 2; ++mt)
                #pragma unroll
                for (int hf = 0; hf < 2; ++hf)
                    part[mt][hf] += __shfl_xor_sync(0xffffffffu, part[mt][hf], off);

        // ---- write partials to this tile's ep buffer ----
        if (qcol == 0) {
            float* epb = ep + (tile & 1) * 256;
            #pragma unroll
            for (int mt = 0; mt < 2; ++mt)
                #pragma unroll
                for (int hf = 0; hf < 2; ++hf) {
                    int row = mgrp * 32 + mt * 16 + hf * 8 + qrow;
                    epb[row * 4 + ngrp] = part[mt][hf];
                }
        }
    }

    // ---- final tile's output ----
    __syncthreads();
    if (t < ROWS_PER_TILE) {
        const float* epb = ep + ((TILES - 1) & 1) * 256;
        float s  = epb[t * 4 + 0] + epb[t * 4 + 1]
                 + epb[t * 4 + 2] + epb[t * 4 + 3];
        float y  = fmaxf(s + b2v, 0.0f);
        int rowg = rowbase0 + (TILES - 1) * ROWS_PER_TILE + t;
        float xv = X[(size_t)rowg * F_TOT + f];
        reinterpret_cast<float2*>(out)[(size_t)rowg * F_TOT + f] =
            make_float2(xv, y);
    }
}

// ---------------- launch ----------------
extern "C" void kernel_launch(void* const* d_in, const int* in_sizes, int n_in,
                              void* d_out, int out_size)
{
    const float* X  = (const float*)d_in[0];
    const float* r_ = (const float*)d_in[1];
    const float* W1 = (const float*)d_in[2];
    const float* b1 = (const float*)d_in[3];
    const float* W2 = (const float*)d_in[4];
    const float* b2 = (const float*)d_in[5];
    float* out = (float*)d_out;

    cudaFuncSetAttribute(cont_mlp_mma_kernel,
                         cudaFuncAttributeMaxDynamicSharedMemorySize, SMEM_BYTES);
    cudaFuncSetAttribute(cont_mlp_mma_kernel,
                         cudaFuncAttributePreferredSharedMemoryCarveout, 100);

    dim3 grid(B_TOT / ROWS_PER_BLK, F_TOT);   // (64, 32)
    cont_mlp_mma_kernel<<<grid, THREADS, SMEM_BYTES>>>(X, r_, W1, b1, W2, b2, out);
}

// round 17
// speedup vs baseline: 1.0958x; 1.0958x over previous
#include <cuda_runtime.h>
#include <cuda_bf16.h>
#include <cstdint>

// ---------------- problem constants ----------------
#define B_TOT 16384
#define F_TOT 32
#define D_IN  64
#define H_HID 128

#define THREADS       256
#define GTILES        4             // tiles per warp-group
#define ROWS_PER_TILE 64
#define ROWS_PER_GRP  (GTILES * ROWS_PER_TILE)   // 256
#define ROWS_PER_BLK  (2 * ROWS_PER_GRP)         // 512

// smem float layout: 4 A buffers (2 groups x double buffer), B [h][k] tf32
#define A_STRIDE  68                      // 272B rows: 8-row LDSM phases distinct
#define B2_STRIDE 68
#define A_FLOATS  (ROWS_PER_TILE * A_STRIDE)   // 4352
#define B_OFF     (4 * A_FLOATS)               // 17408
#define B2_FLOATS (128 * B2_STRIDE)            // 8704
#define B1_OFF    (B_OFF + B2_FLOATS)          // 26112
#define W2_OFF    (B1_OFF + 128)               // 26240
#define EP_OFF    (W2_OFF + 128)               // 26368 : ep[2 grp][2 buf][128]
#define SMEM_FLOATS (EP_OFF + 512)             // 26880
#define SMEM_BYTES  (SMEM_FLOATS * 4)          // 107520 -> 2 CTAs = 215KB < 228KB

__device__ __forceinline__ float to_tf32(float x) {
    float y;
    asm("cvt.rna.tf32.f32 %0, %1;" : "=f"(y) : "f"(x));
    return y;
}
__device__ __forceinline__ uint32_t smem_u32(const void* p) {
    uint32_t a;
    asm("{ .reg .u64 t; cvta.to.shared.u64 t, %1; cvt.u32.u64 %0, t; }" : "=r"(a) : "l"(p));
    return a;
}

#define CP_ASYNC16(dst_u32, src_ptr) \
    asm volatile("cp.async.cg.shared.global [%0], [%1], 16;" \
                 :: "r"(dst_u32), "l"(src_ptr) : "memory")
#define CP_ASYNC_COMMIT() asm volatile("cp.async.commit_group;" ::: "memory")
#define CP_ASYNC_WAIT(n)  asm volatile("cp.async.wait_group %0;" :: "n"(n) : "memory")

// group-local named barrier (ids 1,2), 128 threads each
#define GROUP_BAR(gid) \
    asm volatile("bar.sync %0, %1;" :: "r"((gid) + 1), "r"(128) : "memory")

// ldmatrix (b16 view): 8x8 b16 matrix = 8 rows x 16B; as b32, lane L of
// matrix m receives element (row L/4, col L%4).
#define LDSM_X4(r0, r1, r2, r3, addr) \
    asm volatile("ldmatrix.sync.aligned.m8n8.x4.shared.b16 {%0,%1,%2,%3}, [%4];" \
                 : "=r"(r0), "=r"(r1), "=r"(r2), "=r"(r3) : "r"(addr))

// m16n8k8 row.col tf32 MMA, fp32 accumulate
#define MMA_TF32(c, a, b0r, b1r)                                          \
    asm volatile("mma.sync.aligned.m16n8k8.row.col.f32.tf32.tf32.f32 "    \
                 "{%0,%1,%2,%3}, {%4,%5,%6,%7}, {%8,%9}, {%0,%1,%2,%3};"  \
                 : "+f"((c)[0]), "+f"((c)[1]), "+f"((c)[2]), "+f"((c)[3]) \
                 : "r"((a)[0]), "r"((a)[1]), "r"((a)[2]), "r"((a)[3]),    \
                   "r"(b0r), "r"(b1r))

__global__ void __launch_bounds__(THREADS, 2)
cont_mlp_mma_kernel(const float* __restrict__ X,
                    const float* __restrict__ r_,
                    const float* __restrict__ W1,
                    const float* __restrict__ b1,
                    const float* __restrict__ W2,
                    const float* __restrict__ b2,
                    float* __restrict__ out)
{
    extern __shared__ float sm[];
    float* B_s  = sm + B_OFF;     // [128 h][68 k], tf32
    float* b1s  = sm + B1_OFF;    // [128]
    float* w2s  = sm + W2_OFF;    // [128]
    const uint32_t smb = smem_u32(sm);

    const int f  = blockIdx.y;
    const int t  = threadIdx.x;
    const int wid  = t >> 5;
    const int lane = t & 31;
    const int g    = wid >> 2;      // warp-group 0/1
    const int wg   = wid & 3;       // warp within group
    const int lt   = t & 127;       // thread within group
    const int mgrp = wg & 1;        // rows [mgrp*32, +32) within 64-row tile
    const int ngrp = wg >> 1;       // cols [ngrp*64, +64)
    const int qrow = lane >> 2;
    const int qcol = lane & 3;

    const int growbase = blockIdx.x * ROWS_PER_BLK + g * ROWS_PER_GRP;
    const float* rfeat = r_ + (size_t)f * D_IN;   // row stride = F_TOT*D_IN floats

    // ---- issue cp.async for this group's tile 0 into its buffer 0 ----
    {
        const float* rbase = rfeat + (size_t)growbase * (F_TOT * D_IN);
        uint32_t abuf = smb + (uint32_t)(g * 2 * A_FLOATS * 4);
        #pragma unroll
        for (int i = 0; i < 8; ++i) {
            int idx = lt + i * 128;         // 0..1023 float4 units
            int row = idx >> 4;             // 0..63
            int q   = idx & 15;
            CP_ASYNC16(abuf + (uint32_t)((row * A_STRIDE + q * 4) * 4),
                       rbase + (size_t)row * (F_TOT * D_IN) + q * 4);
        }
        CP_ASYNC_COMMIT();
    }

    // ---- stage B = W1[f] transposed to [h][k], tf32-rounded (all 256 thr) ----
    {
        const float* Wf = W1 + (size_t)f * D_IN * H_HID;
        #pragma unroll
        for (int i = 0; i < 8; ++i) {
            int idx = t + i * THREADS;      // 0..2047
            int h   = idx & 127;            // lane-consecutive -> coalesced LDG
            int d0  = (idx >> 7) * 4;       // k block
            float4 v;
            v.x = to_tf32(Wf[(d0 + 0) * H_HID + h]);
            v.y = to_tf32(Wf[(d0 + 1) * H_HID + h]);
            v.z = to_tf32(Wf[(d0 + 2) * H_HID + h]);
            v.w = to_tf32(Wf[(d0 + 3) * H_HID + h]);
            *reinterpret_cast<float4*>(B_s + h * B2_STRIDE + d0) = v;
        }
    }
    if (t < H_HID) {
        b1s[t] = b1[f * H_HID + t];
        w2s[t] = W2[f * H_HID + t];
    }
    const float b2v = b2[f];
    __syncthreads();                // B/b1s/w2s visible; only full barrier

    // ---- per-thread ldmatrix base addresses ----
    const uint32_t a_base_off = (uint32_t)((
        (mgrp * 32 + (lane & 7) + ((lane >> 3) & 1) * 8) * A_STRIDE
        + (lane >> 4) * 4) * 4);
    const uint32_t b_base = smb + (uint32_t)(B_OFF * 4) + (uint32_t)((
        (ngrp * 64 + (lane & 7) + ((lane >> 4) & 1) * 8) * B2_STRIDE
        + ((lane >> 3) & 1) * 4) * 4);

    float* epg = sm + EP_OFF + g * 256;   // this group's [2][128] partials

    #pragma unroll 1
    for (int tl = 0; tl < GTILES; ++tl) {
        CP_ASYNC_WAIT(0);          // this thread's group(tl) complete
        GROUP_BAR(g);              // A[g][tl&1] visible group-wide; ep(tl-1) ready

        // ---- output for previous tile ----
        if (tl > 0 && lt < ROWS_PER_TILE) {
            const float* epb = epg + ((tl - 1) & 1) * 128;
            float s  = epb[lt * 2 + 0] + epb[lt * 2 + 1];
            float y  = fmaxf(s + b2v, 0.0f);
            int rowg = growbase + (tl - 1) * ROWS_PER_TILE + lt;
            float xv = X[(size_t)rowg * F_TOT + f];
            reinterpret_cast<float2*>(out)[(size_t)rowg * F_TOT + f] =
                make_float2(xv, y);
        }

        // ---- issue cp.async for tile tl+1 (WAR closed by GROUP_BAR above) ----
        if (tl + 1 < GTILES) {
            const float* rbase = rfeat +
                (size_t)(growbase + (tl + 1) * ROWS_PER_TILE) * (F_TOT * D_IN);
            uint32_t abuf = smb + (uint32_t)((g * 2 + ((tl + 1) & 1)) * A_FLOATS * 4);
            #pragma unroll
            for (int i = 0; i < 8; ++i) {
                int idx = lt + i * 128;
                int row = idx >> 4;
                int q   = idx & 15;
                CP_ASYNC16(abuf + (uint32_t)((row * A_STRIDE + q * 4) * 4),
                           rbase + (size_t)row * (F_TOT * D_IN) + q * 4);
            }
            CP_ASYNC_COMMIT();
        }

        float acc[2][8][4];
        #pragma unroll
        for (int mt = 0; mt < 2; ++mt)
            #pragma unroll
            for (int nt = 0; nt < 8; ++nt)
                #pragma unroll
                for (int rr = 0; rr < 4; ++rr)
                    acc[mt][nt][rr] = 0.0f;

        const uint32_t a_base =
            smb + (uint32_t)((g * 2 + (tl & 1)) * A_FLOATS * 4) + a_base_off;

        // ---- k-loop: 8 steps of k=8; LDSM.x4, A rounded in regs ----
        #pragma unroll
        for (int ks = 0; ks < 8; ++ks) {
            uint32_t a[2][4];
            #pragma unroll
            for (int mt = 0; mt < 2; ++mt) {
                LDSM_X4(a[mt][0], a[mt][1], a[mt][2], a[mt][3],
                        a_base + (uint32_t)(mt * 16 * A_STRIDE * 4) + (uint32_t)(ks * 32));
                #pragma unroll
                for (int rr = 0; rr < 4; ++rr)
                    a[mt][rr] = __float_as_uint(to_tf32(__uint_as_float(a[mt][rr])));
            }
            #pragma unroll
            for (int ntp = 0; ntp < 4; ++ntp) {
                uint32_t b0, b1r, b2r, b3r;
                LDSM_X4(b0, b1r, b2r, b3r,
                        b_base + (uint32_t)(ntp * 16 * B2_STRIDE * 4) + (uint32_t)(ks * 32));
                #pragma unroll
                for (int mt = 0; mt < 2; ++mt) {
                    MMA_TF32(acc[mt][2 * ntp + 0], a[mt], b0, b1r);
                    MMA_TF32(acc[mt][2 * ntp + 1], a[mt], b2r, b3r);
                }
            }
        }

        // ---- epilogue: relu(+b1)*w2, sum over this warp's 64 cols ----
        float part[2][2] = {{0.0f, 0.0f}, {0.0f, 0.0f}};
        #pragma unroll
        for (int nt = 0; nt < 8; ++nt) {
            int c = ngrp * 64 + nt * 8 + qcol * 2;
            float2 bp = *reinterpret_cast<const float2*>(b1s + c);
            float2 wp = *reinterpret_cast<const float2*>(w2s + c);
            #pragma unroll
            for (int mt = 0; mt < 2; ++mt)
                #pragma unroll
                for (int hf = 0; hf < 2; ++hf) {
                    float d0 = fmaxf(acc[mt][nt][hf * 2 + 0] + bp.x, 0.0f);
                    float d1 = fmaxf(acc[mt][nt][hf * 2 + 1] + bp.y, 0.0f);
                    part[mt][hf] = fmaf(d0, wp.x, part[mt][hf]);
                    part[mt][hf] = fmaf(d1, wp.y, part[mt][hf]);
                }
        }
        #pragma unroll
        for (int off = 1; off < 4; off <<= 1)
            #pragma unroll
            for (int mt = 0; mt < 2; ++mt)
                #pragma unroll
                for (int hf = 0; hf < 2; ++hf)
                    part[mt][hf] += __shfl_xor_sync(0xffffffffu, part[mt][hf], off);

        if (qcol == 0) {
            float* epb = epg + (tl & 1) * 128;
            #pragma unroll
            for (int mt = 0; mt < 2; ++mt)
                #pragma unroll
                for (int hf = 0; hf < 2; ++hf) {
                    int row = mgrp * 32 + mt * 16 + hf * 8 + qrow;
                    epb[row * 2 + ngrp] = part[mt][hf];
                }
        }
    }

    // ---- final tile's output ----
    GROUP_BAR(g);
    if (lt < ROWS_PER_TILE) {
        const float* epb = epg + ((GTILES - 1) & 1) * 128;
        float s  = epb[lt * 2 + 0] + epb[lt * 2 + 1];
        float y  = fmaxf(s + b2v, 0.0f);
        int rowg = growbase + (GTILES - 1) * ROWS_PER_TILE + lt;
        float xv = X[(size_t)rowg * F_TOT + f];
        reinterpret_cast<float2*>(out)[(size_t)rowg * F_TOT + f] =
            make_float2(xv, y);
    }
}

// ---------------- launch ----------------
extern "C" void kernel_launch(void* const* d_in, const int* in_sizes, int n_in,
                              void* d_out, int out_size)
{
    const float* X  = (const float*)d_in[0];
    const float* r_ = (const float*)d_in[1];
    const float* W1 = (const float*)d_in[2];
    const float* b1 = (const float*)d_in[3];
    const float* W2 = (const float*)d_in[4];
    const float* b2 = (const float*)d_in[5];
    float* out = (float*)d_out;

    cudaFuncSetAttribute(cont_mlp_mma_kernel,
                         cudaFuncAttributeMaxDynamicSharedMemorySize, SMEM_BYTES);
    cudaFuncSetAttribute(cont_mlp_mma_kernel,
                         cudaFuncAttributePreferredSharedMemoryCarveout, 100);

    dim3 grid(B_TOT / ROWS_PER_BLK, F_TOT);   // (32, 32)
    cont_mlp_mma_kernel<<<grid, THREADS, SMEM_BYTES>>>(X, r_, W1, b1, W2, b2, out);
}